// round 8
// baseline (speedup 1.0000x reference)
#include <cuda_runtime.h>
#include <cstdint>

// ---------------------------------------------------------------------------
// Problem constants
// ---------------------------------------------------------------------------
#define NN 100000
#define EE 1600000
#define HH 128
#define H2 256
#define GG 512
#define LL 3
#define BN_EPS 1e-5f
#define MTILES 782                    // ceil(100000/128)

// ---------------------------------------------------------------------------
// Scratch (device globals; no dynamic allocation allowed)
// ---------------------------------------------------------------------------
__device__ float g_z[(size_t)NN * HH];
__device__ float g_h[(size_t)NN * HH];
__device__ float g_t[(size_t)NN * H2];
__device__ float g_u[(size_t)NN * HH];
__device__ float g_f[(size_t)NN * HH];
__device__ float g_colsum[H2];
__device__ float g_colsq[H2];
__device__ float g_scaleA[H2];
__device__ float g_shiftA[H2];
__device__ float g_scaleB[HH];
__device__ float g_shiftB[HH];
__device__ float g_vf[GG * HH];
__device__ float g_pooled[GG * HH];
__device__ float g_vt2[GG * H2];
__device__ float g_vt1[GG * HH];
__device__ float g_counts[GG];
__device__ float g_vscale[H2];
__device__ float g_vshift[H2];
__device__ int   g_is64;
// 3xTF32 weights: per layer W1' = [384][256], W2' = [768][128]
// row pattern per original k: 3k = hi, 3k+1 = lo, 3k+2 = hi
__device__ float g_w1t[LL * 384 * 256];
__device__ float g_w2t[LL * 768 * 128];

// ---------------------------------------------------------------------------
// dtype detect (int64 vs int32 indices)
// ---------------------------------------------------------------------------
__global__ void detect_kernel(const int* __restrict__ ei32, int* __restrict__ flag) {
    __shared__ int any;
    if (threadIdx.x == 0) any = 0;
    __syncthreads();
    int v = ei32[2 * threadIdx.x + 1];
    if (v != 0) atomicOr(&any, 1);
    __syncthreads();
    if (threadIdx.x == 0) *flag = any ? 0 : 1;
}
__device__ __forceinline__ int load_index(const void* __restrict__ p, size_t i, int is64) {
    if (is64) return (int)reinterpret_cast<const long long*>(p)[i];
    return reinterpret_cast<const int*>(p)[i];
}

// ---------------------------------------------------------------------------
// tf32 helpers
// ---------------------------------------------------------------------------
__device__ __forceinline__ void tf32_split(float a, float& hif, float& lof) {
    uint32_t hi;
    asm("cvt.rna.tf32.f32 %0, %1;" : "=r"(hi) : "f"(a));
    hif = __uint_as_float(hi);
    float lo = a - hif;
    uint32_t lob;
    asm("cvt.rna.tf32.f32 %0, %1;" : "=r"(lob) : "f"(lo));
    lof = __uint_as_float(lob);
}

// ---------------------------------------------------------------------------
// Weight conversion: split into [3K][N] rows (hi, lo, hi per original k)
// ---------------------------------------------------------------------------
__global__ void convw_kernel(const float* __restrict__ w1, const float* __restrict__ w2,
                             float* __restrict__ o1, float* __restrict__ o2) {
    int idx = blockIdx.x * blockDim.x + threadIdx.x;
    if (idx >= LL * HH * H2) return;
    int l = idx / (HH * H2);
    int rem = idx % (HH * H2);
    {   // W1[l][k][n] (k<128, n<256)
        int k = rem >> 8, n = rem & 255;
        float hi, lo;
        tf32_split(w1[idx], hi, lo);
        float* base = o1 + (size_t)l * 384 * 256;
        base[(3 * k + 0) * 256 + n] = hi;
        base[(3 * k + 1) * 256 + n] = lo;
        base[(3 * k + 2) * 256 + n] = hi;
    }
    {   // W2[l][kk][n] (kk<256, n<128)
        int kk = rem >> 7, n = rem & 127;
        float hi, lo;
        tf32_split(w2[idx], hi, lo);
        float* base = o2 + (size_t)l * 768 * 128;
        base[(3 * kk + 0) * 128 + n] = hi;
        base[(3 * kk + 1) * 128 + n] = lo;
        base[(3 * kk + 2) * 128 + n] = hi;
    }
}

// ---------------------------------------------------------------------------
// 3xTF32 mma.sync GEMM: out[M,CN] = act(A)[M,K] @ W + bias
// A split cols per k: [hi, hi, lo] ; B rows per k: [hi, lo, hi]
//   => k'=3k: hi*hi, 3k+1: hi*lo, 3k+2: lo*hi  (lo*lo dropped, ~2^-22)
// Block: 256 thr = 8 warps (4x2), tile 128x128, chunk = 8 orig k = 24 k'.
// TRANS: BN+ReLU fused into A split (GEMM2).
// ---------------------------------------------------------------------------
template <int KCH, int CN, bool TRANS>
__global__ void __launch_bounds__(256)
mma_gemm(const float* __restrict__ A, const float* __restrict__ Bw,
         const float* __restrict__ bias, float* __restrict__ out, int M,
         const float* __restrict__ tsc, const float* __restrict__ tsh) {
    __shared__ float A_s[128][28];     // [m][k'=24], pad 4
    __shared__ float B_s[24][132];     // [k'][n], pad 4
    __shared__ float s_scale[H2];
    __shared__ float s_shift[H2];
    __shared__ float s_bias[128];

    const int K = KCH * 8;             // original K
    int tid = threadIdx.x;
    int lane = tid & 31;
    int warp = tid >> 5;
    int wr = warp >> 1;                // 0..3 (32-row group)
    int wc = warp & 1;                 // 0..1 (64-col group)
    int row0 = blockIdx.x * 128;
    int col0 = blockIdx.y * 128;

    if (TRANS) {
        for (int i = tid; i < K; i += 256) { s_scale[i] = tsc[i]; s_shift[i] = tsh[i]; }
    }
    if (tid < 128) s_bias[tid] = bias[col0 + tid];

    // prefetch registers
    float4 ga;                         // 128 rows x 8 k = 256 float4 (1/thread)
    float4 gb[3];                      // 24 k' x 128 n = 768 float4 (3/thread)
    int arow_l = tid >> 1;             // 0..127
    int aq = tid & 1;                  // float4 within the 8-k chunk

    auto loadG = [&](int ch) {
        float4 v = make_float4(0.f, 0.f, 0.f, 0.f);
        if (row0 + arow_l < M)
            v = *reinterpret_cast<const float4*>(
                &A[(size_t)(row0 + arow_l) * K + ch * 8 + aq * 4]);
        ga = v;
#pragma unroll
        for (int r = 0; r < 3; r++) {
            int idx = tid + 256 * r;
            int kr = idx >> 5, c4 = idx & 31;
            gb[r] = *reinterpret_cast<const float4*>(
                &Bw[(size_t)(ch * 24 + kr) * CN + col0 + c4 * 4]);
        }
    };
    auto storeS = [&](int ch) {
        float f[4] = {ga.x, ga.y, ga.z, ga.w};
#pragma unroll
        for (int j = 0; j < 4; j++) {
            int kl = aq * 4 + j;       // 0..7 within chunk
            float a = f[j];
            if (TRANS) {
                int kk = ch * 8 + kl;
                a = fmaxf(a * s_scale[kk] + s_shift[kk], 0.f);
            }
            float hi, lo;
            tf32_split(a, hi, lo);
            A_s[arow_l][3 * kl + 0] = hi;
            A_s[arow_l][3 * kl + 1] = hi;
            A_s[arow_l][3 * kl + 2] = lo;
        }
#pragma unroll
        for (int r = 0; r < 3; r++) {
            int idx = tid + 256 * r;
            int kr = idx >> 5, c4 = idx & 31;
            *reinterpret_cast<float4*>(&B_s[kr][c4 * 4]) = gb[r];
        }
    };

    float acc[2][8][4];
#pragma unroll
    for (int mi = 0; mi < 2; mi++)
#pragma unroll
        for (int ni = 0; ni < 8; ni++)
#pragma unroll
            for (int q = 0; q < 4; q++) acc[mi][ni][q] = 0.f;

    loadG(0);
    __syncthreads();          // s_scale/s_bias visible
    storeS(0);

    for (int ch = 0; ch < KCH; ch++) {
        __syncthreads();      // smem tile ready
        if (ch + 1 < KCH) loadG(ch + 1);
#pragma unroll
        for (int ks = 0; ks < 3; ks++) {
            int kb = ks * 8;
            uint32_t bfr[8][2];
            int bn = lane >> 2;
            int bk = kb + (lane & 3);
#pragma unroll
            for (int ni = 0; ni < 8; ni++) {
                int n = wc * 64 + ni * 8 + bn;
                bfr[ni][0] = __float_as_uint(B_s[bk][n]);
                bfr[ni][1] = __float_as_uint(B_s[bk + 4][n]);
            }
#pragma unroll
            for (int mi = 0; mi < 2; mi++) {
                int r = wr * 32 + mi * 16 + (lane >> 2);
                int c = kb + (lane & 3);
                uint32_t a0 = __float_as_uint(A_s[r][c]);
                uint32_t a1 = __float_as_uint(A_s[r + 8][c]);
                uint32_t a2 = __float_as_uint(A_s[r][c + 4]);
                uint32_t a3 = __float_as_uint(A_s[r + 8][c + 4]);
#pragma unroll
                for (int ni = 0; ni < 8; ni++) {
                    asm volatile(
                        "mma.sync.aligned.m16n8k8.row.col.f32.tf32.tf32.f32 "
                        "{%0,%1,%2,%3}, {%4,%5,%6,%7}, {%8,%9}, {%0,%1,%2,%3};\n"
                        : "+f"(acc[mi][ni][0]), "+f"(acc[mi][ni][1]),
                          "+f"(acc[mi][ni][2]), "+f"(acc[mi][ni][3])
                        : "r"(a0), "r"(a1), "r"(a2), "r"(a3),
                          "r"(bfr[ni][0]), "r"(bfr[ni][1]));
                }
            }
        }
        __syncthreads();      // compute done before overwrite
        if (ch + 1 < KCH) storeS(ch + 1);
    }

    // epilogue: D + bias -> out
    int rb = row0 + wr * 32 + (lane >> 2);
    int cb = wc * 64 + (lane & 3) * 2;
#pragma unroll
    for (int mi = 0; mi < 2; mi++) {
        int r = rb + mi * 16;
#pragma unroll
        for (int ni = 0; ni < 8; ni++) {
            int cl = cb + ni * 8;
            float2 o0, o1;
            o0.x = acc[mi][ni][0] + s_bias[cl];
            o0.y = acc[mi][ni][1] + s_bias[cl + 1];
            o1.x = acc[mi][ni][2] + s_bias[cl];
            o1.y = acc[mi][ni][3] + s_bias[cl + 1];
            if (r < M)
                *reinterpret_cast<float2*>(&out[(size_t)r * CN + col0 + cl]) = o0;
            if (r + 8 < M)
                *reinterpret_cast<float2*>(&out[(size_t)(r + 8) * CN + col0 + cl]) = o1;
        }
    }
}

// ---------------------------------------------------------------------------
// init / copy
// ---------------------------------------------------------------------------
__global__ void init_kernel(const float* __restrict__ vn_emb, float* __restrict__ out_readout,
                            float* __restrict__ vf, float* __restrict__ pooled,
                            float* __restrict__ counts,
                            float* __restrict__ colsum, float* __restrict__ colsq) {
    int idx = blockIdx.x * blockDim.x + threadIdx.x;
    if (idx < GG * HH) {
        pooled[idx] = 0.f;
        out_readout[idx] = 0.f;
        vf[idx] = __ldg(&vn_emb[idx & (HH - 1)]);
    }
    if (idx < GG) counts[idx] = 0.f;
    if (idx < H2) { colsum[idx] = 0.f; colsq[idx] = 0.f; }
}

__global__ void copyz_kernel(const float* __restrict__ x, float* __restrict__ z) {
    size_t i = (size_t)blockIdx.x * blockDim.x + threadIdx.x;
    if (i < (size_t)NN * HH / 4)
        reinterpret_cast<float4*>(z)[i] = reinterpret_cast<const float4*>(x)[i];
}

// ---------------------------------------------------------------------------
// Edge scatter: 8 edges per warp, all gathers in flight before atomics
// ---------------------------------------------------------------------------
__global__ void scatter_kernel(const float* __restrict__ h, float* __restrict__ z,
                               const void* __restrict__ ei, int E,
                               const int* __restrict__ is64p) {
    int w = (int)(((size_t)blockIdx.x * blockDim.x + threadIdx.x) >> 5);
    int lane = threadIdx.x & 31;
    int Q = E >> 3;
    if (w >= Q) return;
    int is64 = *is64p;
    int src[8], dst[8];
#pragma unroll
    for (int e = 0; e < 8; e++) src[e] = load_index(ei, (size_t)(w + e * Q), is64);
#pragma unroll
    for (int e = 0; e < 8; e++) dst[e] = load_index(ei, (size_t)E + (w + e * Q), is64);
    float4 v[8];
#pragma unroll
    for (int e = 0; e < 8; e++)
        v[e] = *reinterpret_cast<const float4*>(&h[(size_t)src[e] * HH + lane * 4]);
#pragma unroll
    for (int e = 0; e < 8; e++)
        atomicAdd(reinterpret_cast<float4*>(&z[(size_t)dst[e] * HH + lane * 4]), v[e]);
}

// ---------------------------------------------------------------------------
// BN column stats + finalize
// ---------------------------------------------------------------------------
template <int C>
__global__ void colstats_kernel(const float* __restrict__ X, int Nrows,
                                float* __restrict__ sum, float* __restrict__ sq) {
    int c = threadIdx.x;
    float s = 0.f, q = 0.f;
    for (int r = blockIdx.x; r < Nrows; r += gridDim.x) {
        float v = X[(size_t)r * C + c];
        s += v;
        q += v * v;
    }
    atomicAdd(&sum[c], s);
    atomicAdd(&sq[c], q);
}

__global__ void bn_finalize_kernel(float* __restrict__ sum, float* __restrict__ sq,
                                   const float* __restrict__ g, const float* __restrict__ b,
                                   float* __restrict__ scale, float* __restrict__ shift,
                                   int C, float invN) {
    int c = threadIdx.x;
    if (c < C) {
        float m = sum[c] * invN;
        float v = sq[c] * invN - m * m;
        float sc = __ldg(&g[c]) * rsqrtf(v + BN_EPS);
        scale[c] = sc;
        shift[c] = __ldg(&b[c]) - m * sc;
        sum[c] = 0.f;
        sq[c] = 0.f;
    }
}

// ---------------------------------------------------------------------------
// Per-layer finalize / prep kernels
// ---------------------------------------------------------------------------
__global__ void prep0_kernel(const float* __restrict__ u, const float* __restrict__ sc,
                             const float* __restrict__ sh, const float* __restrict__ vn_emb,
                             float* __restrict__ h, float* __restrict__ z) {
    size_t idx = (size_t)blockIdx.x * blockDim.x + threadIdx.x;
    if (idx >= (size_t)NN * (HH / 4)) return;
    int c = (int)(idx & 31) * 4;
    float4 v = reinterpret_cast<const float4*>(u)[idx];
    float4 r;
    r.x = fmaxf(v.x * sc[c + 0] + sh[c + 0], 0.f) + __ldg(&vn_emb[c + 0]);
    r.y = fmaxf(v.y * sc[c + 1] + sh[c + 1], 0.f) + __ldg(&vn_emb[c + 1]);
    r.z = fmaxf(v.z * sc[c + 2] + sh[c + 2], 0.f) + __ldg(&vn_emb[c + 2]);
    r.w = fmaxf(v.w * sc[c + 3] + sh[c + 3], 0.f) + __ldg(&vn_emb[c + 3]);
    reinterpret_cast<float4*>(h)[idx] = r;
    reinterpret_cast<float4*>(z)[idx] = r;
}

__global__ void fin1_kernel(const float* __restrict__ u, const float* __restrict__ sc,
                            const float* __restrict__ sh, float* __restrict__ f,
                            const void* __restrict__ batch, float* __restrict__ pooled,
                            const int* __restrict__ is64p) {
    size_t idx = (size_t)blockIdx.x * blockDim.x + threadIdx.x;
    if (idx >= (size_t)NN * (HH / 4)) return;
    int n = (int)(idx >> 5);
    int c = (int)(idx & 31) * 4;
    float4 v = reinterpret_cast<const float4*>(u)[idx];
    float4 r;
    r.x = fmaxf(v.x * sc[c + 0] + sh[c + 0], 0.f);
    r.y = fmaxf(v.y * sc[c + 1] + sh[c + 1], 0.f);
    r.z = fmaxf(v.z * sc[c + 2] + sh[c + 2], 0.f);
    r.w = fmaxf(v.w * sc[c + 3] + sh[c + 3], 0.f);
    reinterpret_cast<float4*>(f)[idx] = r;
    int g = load_index(batch, n, *is64p);
    atomicAdd(reinterpret_cast<float4*>(&pooled[(size_t)g * HH + c]), r);
}

__global__ void prep1_kernel(const float* __restrict__ f, const float* __restrict__ vf,
                             const void* __restrict__ batch,
                             float* __restrict__ h, float* __restrict__ z,
                             const int* __restrict__ is64p) {
    size_t idx = (size_t)blockIdx.x * blockDim.x + threadIdx.x;
    if (idx >= (size_t)NN * (HH / 4)) return;
    int n = (int)(idx >> 5);
    int c = (int)(idx & 31) * 4;
    int g = load_index(batch, n, *is64p);
    float4 a = reinterpret_cast<const float4*>(f)[idx];
    float4 b = *reinterpret_cast<const float4*>(&vf[(size_t)g * HH + c]);
    float4 r;
    r.x = a.x + b.x; r.y = a.y + b.y; r.z = a.z + b.z; r.w = a.w + b.w;
    reinterpret_cast<float4*>(h)[idx] = r;
    reinterpret_cast<float4*>(z)[idx] = r;
}

__global__ void fin2_kernel(const float* __restrict__ u, const float* __restrict__ sc,
                            const float* __restrict__ sh, float* __restrict__ out_feats,
                            const void* __restrict__ batch,
                            float* __restrict__ readout, float* __restrict__ counts,
                            const int* __restrict__ is64p) {
    size_t idx = (size_t)blockIdx.x * blockDim.x + threadIdx.x;
    if (idx >= (size_t)NN * (HH / 4)) return;
    int n = (int)(idx >> 5);
    int c = (int)(idx & 31) * 4;
    float4 v = reinterpret_cast<const float4*>(u)[idx];
    float4 r;
    r.x = v.x * sc[c + 0] + sh[c + 0];
    r.y = v.y * sc[c + 1] + sh[c + 1];
    r.z = v.z * sc[c + 2] + sh[c + 2];
    r.w = v.w * sc[c + 3] + sh[c + 3];
    reinterpret_cast<float4*>(out_feats)[idx] = r;
    int g = load_index(batch, n, *is64p);
    atomicAdd(reinterpret_cast<float4*>(&readout[(size_t)g * HH + c]), r);
    if (c == 0) atomicAdd(&counts[g], 1.0f);
}

__global__ void epilogue_kernel(float* __restrict__ readout, const float* __restrict__ counts,
                                const float* __restrict__ vf, float* __restrict__ vf_out) {
    int idx = blockIdx.x * blockDim.x + threadIdx.x;
    if (idx < GG * HH) {
        float cnt = fmaxf(counts[idx >> 7], 1.0f);
        readout[idx] = readout[idx] / cnt;
        vf_out[idx] = vf[idx];
    }
}

// ---------------------------------------------------------------------------
// Virtual-node MLP kernels (tiny: G=512 rows)
// ---------------------------------------------------------------------------
__global__ void vgemm1_kernel(const float* __restrict__ pooled, const float* __restrict__ vf,
                              const float* __restrict__ W, const float* __restrict__ b,
                              float* __restrict__ out) {
    int g = blockIdx.x;
    int c = threadIdx.x;
    __shared__ float a[HH];
    if (c < HH) a[c] = pooled[g * HH + c] + vf[g * HH + c];
    __syncthreads();
    float acc = __ldg(&b[c]);
#pragma unroll 8
    for (int k = 0; k < HH; k++) acc = fmaf(a[k], __ldg(&W[k * H2 + c]), acc);
    out[g * H2 + c] = acc;
}

__global__ void vgemm2_kernel(const float* __restrict__ vt2, const float* __restrict__ vs,
                              const float* __restrict__ vsh, const float* __restrict__ W,
                              const float* __restrict__ b, float* __restrict__ out) {
    int g = blockIdx.x;
    int c = threadIdx.x;
    __shared__ float a[H2];
    for (int k = c; k < H2; k += HH)
        a[k] = fmaxf(vt2[g * H2 + k] * vs[k] + vsh[k], 0.f);
    __syncthreads();
    float acc = __ldg(&b[c]);
#pragma unroll 8
    for (int k = 0; k < H2; k++) acc = fmaf(a[k], __ldg(&W[k * HH + c]), acc);
    out[g * HH + c] = acc;
}

__global__ void vapply_kernel(const float* __restrict__ vt1, const float* __restrict__ vs,
                              const float* __restrict__ vsh, float* __restrict__ vf) {
    int idx = blockIdx.x * blockDim.x + threadIdx.x;
    if (idx < GG * HH) {
        int c = idx & (HH - 1);
        vf[idx] = fmaxf(vt1[idx] * vs[c] + vsh[c], 0.f);
    }
}

// ---------------------------------------------------------------------------
// Host driver
// ---------------------------------------------------------------------------
extern "C" void kernel_launch(void* const* d_in, const int* in_sizes, int n_in,
                              void* d_out, int out_size) {
    int off = (n_in > 3 && in_sizes[3] <= 4) ? 1 : 0;
    const float* x            = (const float*)d_in[0];
    const void*  ei           = d_in[1];
    const void*  batch        = d_in[2];
    const float* conv_w1      = (const float*)d_in[3 + off];
    const float* conv_b1      = (const float*)d_in[4 + off];
    const float* conv_bn_g    = (const float*)d_in[5 + off];
    const float* conv_bn_b    = (const float*)d_in[6 + off];
    const float* conv_w2      = (const float*)d_in[7 + off];
    const float* conv_b2      = (const float*)d_in[8 + off];
    const float* bn_g         = (const float*)d_in[9 + off];
    const float* bn_b         = (const float*)d_in[10 + off];
    const float* vn_emb       = (const float*)d_in[11 + off];
    const float* vmlp_w1      = (const float*)d_in[12 + off];
    const float* vmlp_b1      = (const float*)d_in[13 + off];
    const float* vmlp_bn1_g   = (const float*)d_in[14 + off];
    const float* vmlp_bn1_b   = (const float*)d_in[15 + off];
    const float* vmlp_w2      = (const float*)d_in[16 + off];
    const float* vmlp_b2      = (const float*)d_in[17 + off];
    const float* vmlp_bn2_g   = (const float*)d_in[18 + off];
    const float* vmlp_bn2_b   = (const float*)d_in[19 + off];

    float* out = (float*)d_out;
    float* out_feats = out;
    float* out_readout = out + (size_t)NN * HH;
    float* out_vf = out_readout + GG * HH;

    float *p_z, *p_h, *p_t, *p_u, *p_f, *p_colsum, *p_colsq, *p_scaleA, *p_shiftA,
          *p_scaleB, *p_shiftB, *p_vf, *p_pooled, *p_vt2, *p_vt1, *p_counts,
          *p_vscale, *p_vshift, *p_w1t, *p_w2t;
    int* p_is64;
    cudaGetSymbolAddress((void**)&p_z, g_z);
    cudaGetSymbolAddress((void**)&p_h, g_h);
    cudaGetSymbolAddress((void**)&p_t, g_t);
    cudaGetSymbolAddress((void**)&p_u, g_u);
    cudaGetSymbolAddress((void**)&p_f, g_f);
    cudaGetSymbolAddress((void**)&p_colsum, g_colsum);
    cudaGetSymbolAddress((void**)&p_colsq, g_colsq);
    cudaGetSymbolAddress((void**)&p_scaleA, g_scaleA);
    cudaGetSymbolAddress((void**)&p_shiftA, g_shiftA);
    cudaGetSymbolAddress((void**)&p_scaleB, g_scaleB);
    cudaGetSymbolAddress((void**)&p_shiftB, g_shiftB);
    cudaGetSymbolAddress((void**)&p_vf, g_vf);
    cudaGetSymbolAddress((void**)&p_pooled, g_pooled);
    cudaGetSymbolAddress((void**)&p_vt2, g_vt2);
    cudaGetSymbolAddress((void**)&p_vt1, g_vt1);
    cudaGetSymbolAddress((void**)&p_counts, g_counts);
    cudaGetSymbolAddress((void**)&p_vscale, g_vscale);
    cudaGetSymbolAddress((void**)&p_vshift, g_vshift);
    cudaGetSymbolAddress((void**)&p_is64, g_is64);
    cudaGetSymbolAddress((void**)&p_w1t, g_w1t);
    cudaGetSymbolAddress((void**)&p_w2t, g_w2t);

    const int M = NN;
    const float invN = 1.0f / (float)NN;
    const float invG = 1.0f / (float)GG;
    int ew_blocks = (NN * (HH / 4) + 255) / 256;
    int sc_blocks = ((EE / 8) + 7) / 8;     // 8 edges per warp, 8 warps/block

    detect_kernel<<<1, 1024>>>((const int*)ei, p_is64);
    convw_kernel<<<(LL * HH * H2 + 255) / 256, 256>>>(conv_w1, conv_w2, p_w1t, p_w2t);
    init_kernel<<<(GG * HH + 255) / 256, 256>>>(vn_emb, out_readout, p_vf, p_pooled,
                                                p_counts, p_colsum, p_colsq);
    copyz_kernel<<<(NN * HH / 4 + 255) / 256, 256>>>(x, p_z);

    for (int l = 0; l < LL; l++) {
        const float* b1 = conv_b1 + l * H2;
        const float* cg = conv_bn_g + l * H2;
        const float* cb = conv_bn_b + l * H2;
        const float* b2 = conv_b2 + l * HH;
        const float* og = bn_g + l * HH;
        const float* ob = bn_b + l * HH;
        const float* w1t = p_w1t + (size_t)l * 384 * 256;
        const float* w2t = p_w2t + (size_t)l * 768 * 128;

        const float* hsrc = (l == 0) ? x : p_h;
        scatter_kernel<<<sc_blocks, 256>>>(hsrc, p_z, ei, EE, p_is64);

        // GEMM1: t = z @ W1 + b1   (3xTF32, K=128 -> 16 chunks of 8, CN=256)
        mma_gemm<16, H2, false><<<dim3(MTILES, 2), 256>>>(p_z, w1t, b1, p_t, M,
                                                          nullptr, nullptr);
        colstats_kernel<H2><<<512, H2>>>(p_t, M, p_colsum, p_colsq);
        bn_finalize_kernel<<<1, 256>>>(p_colsum, p_colsq, cg, cb, p_scaleA, p_shiftA,
                                       H2, invN);

        // GEMM2: u = relu(bn(t)) @ W2 + b2  (K=256 -> 32 chunks, CN=128)
        mma_gemm<32, HH, true><<<dim3(MTILES, 1), 256>>>(p_t, w2t, b2, p_u, M,
                                                         p_scaleA, p_shiftA);
        colstats_kernel<HH><<<512, HH>>>(p_u, M, p_colsum, p_colsq);
        bn_finalize_kernel<<<1, 256>>>(p_colsum, p_colsq, og, ob, p_scaleB, p_shiftB,
                                       HH, invN);

        if (l == 0) {
            prep0_kernel<<<ew_blocks, 256>>>(p_u, p_scaleB, p_shiftB, vn_emb, p_h, p_z);
        } else if (l == 1) {
            fin1_kernel<<<ew_blocks, 256>>>(p_u, p_scaleB, p_shiftB, p_f, batch, p_pooled,
                                            p_is64);
            vgemm1_kernel<<<GG, H2>>>(p_pooled, p_vf, vmlp_w1, vmlp_b1, p_vt2);
            colstats_kernel<H2><<<64, H2>>>(p_vt2, GG, p_colsum, p_colsq);
            bn_finalize_kernel<<<1, 256>>>(p_colsum, p_colsq, vmlp_bn1_g, vmlp_bn1_b,
                                           p_vscale, p_vshift, H2, invG);
            vgemm2_kernel<<<GG, HH>>>(p_vt2, p_vscale, p_vshift, vmlp_w2, vmlp_b2, p_vt1);
            colstats_kernel<HH><<<64, HH>>>(p_vt1, GG, p_colsum, p_colsq);
            bn_finalize_kernel<<<1, 256>>>(p_colsum, p_colsq, vmlp_bn2_g, vmlp_bn2_b,
                                           p_vscale, p_vshift, HH, invG);
            vapply_kernel<<<(GG * HH + 255) / 256, 256>>>(p_vt1, p_vscale, p_vshift, p_vf);
            prep1_kernel<<<ew_blocks, 256>>>(p_f, p_vf, batch, p_h, p_z, p_is64);
        } else {
            fin2_kernel<<<ew_blocks, 256>>>(p_u, p_scaleB, p_shiftB, out_feats, batch,
                                            out_readout, p_counts, p_is64);
        }
    }

    epilogue_kernel<<<(GG * HH + 255) / 256, 256>>>(out_readout, p_counts, p_vf, out_vf);
    (void)in_sizes; (void)n_in; (void)out_size;
}